// round 13
// baseline (speedup 1.0000x reference)
#include <cuda_runtime.h>
#include <cuda_fp16.h>
#include <math.h>
#include <stdint.h>

// ---------------------------------------------------------------------------
// Problem constants
// ---------------------------------------------------------------------------
#define BATCH 8
#define ICH   256
#define NFC   128
#define NPIX  1024
#define KCONV 4096
#define MROWS 8192

// ---------------------------------------------------------------------------
// Device scratch (pure fp16 chain)
// ---------------------------------------------------------------------------
__device__ __half g_w1[ICH * KCONV];
__device__ __half g_wf[NFC * ICH];
__device__ __half g_ws[NFC * ICH];
__device__ __half g_wg[NFC * ICH];

__device__ __half g_x[MROWS * KCONV];          // im2col(x)
__device__ __half g_y[MROWS * ICH];            // conv out
__device__ __half g_fai[BATCH * NPIX * NFC];
__device__ __half g_sit[BATCH * NPIX * NFC];
__device__ __half g_gT[BATCH * NFC * NPIX];    // [b][c][m]
__device__ __half g_S[BATCH * NPIX * NPIX];    // [b][n][m]
__device__ float g_att0[BATCH * NPIX * NFC];   // split-K partials
__device__ float g_att1[BATCH * NPIX * NFC];

// ---------------------------------------------------------------------------
// Portable helpers (base sm_103)
// ---------------------------------------------------------------------------
__device__ __forceinline__ uint32_t smem_u32(const void* p) {
    uint32_t a;
    asm("{ .reg .u64 t; cvta.to.shared.u64 t, %1; cvt.u32.u64 %0, t; }" : "=r"(a) : "l"(p));
    return a;
}

__device__ __forceinline__ void cp16(uint32_t saddr, const void* gaddr) {
    asm volatile("cp.async.cg.shared.global [%0], [%1], 16;" :: "r"(saddr), "l"(gaddr));
}
#define CP_COMMIT() asm volatile("cp.async.commit_group;" ::: "memory")
#define CP_WAIT(n)  asm volatile("cp.async.wait_group %0;" :: "n"(n) : "memory")

__device__ __forceinline__ void ldsm_x4(uint32_t& r0, uint32_t& r1, uint32_t& r2, uint32_t& r3,
                                        uint32_t addr) {
    asm volatile("ldmatrix.sync.aligned.m8n8.x4.shared.b16 {%0,%1,%2,%3}, [%4];"
        : "=r"(r0), "=r"(r1), "=r"(r2), "=r"(r3) : "r"(addr));
}

__device__ __forceinline__ void mma_f16(float* c, const uint32_t* a,
                                        uint32_t b0, uint32_t b1) {
    asm volatile(
        "mma.sync.aligned.m16n8k16.row.col.f32.f16.f16.f32 "
        "{%0,%1,%2,%3}, {%4,%5,%6,%7}, {%8,%9}, {%0,%1,%2,%3};"
        : "+f"(c[0]), "+f"(c[1]), "+f"(c[2]), "+f"(c[3])
        : "r"(a[0]), "r"(a[1]), "r"(a[2]), "r"(a[3]), "r"(b0), "r"(b1));
}

__device__ __forceinline__ uint32_t packh2(float a, float b) {
    __half h0 = __float2half_rn(a), h1 = __float2half_rn(b);
    return (uint32_t)__half_as_ushort(h0) | ((uint32_t)__half_as_ushort(h1) << 16);
}

// ---------------------------------------------------------------------------
// 128x64 pure-fp16 GEMM tile, K-tile = 64 (R6 pipeline ordering)
//   smem/stage: A[128 rows x 64 fp16, stride 144] + B[64 rows x 64, stride 144]
// ---------------------------------------------------------------------------
#define RS64   144
#define SS_B   (128 * RS64)              // 18432
#define SS_STG (SS_B + 64 * RS64)        // 27648
#define GEMM_SMEM_SS (2 * SS_STG)        // 55296

__device__ __forceinline__ void gemm_tile_ss(
    const __half* __restrict__ A, int lda,
    const __half* __restrict__ B, int ldb,
    int K, uint32_t sbase, float acc[2][4][4])
{
    const int tid = threadIdx.x;
    const int l = tid & 31;
    const int wid = tid >> 5;
    const int warp_m = wid & 3, warp_n = wid >> 2;

    const uint32_t a_row = (uint32_t)(warp_m * 32 + (l & 15));
    const uint32_t a_co  = (uint32_t)((l >> 4) << 4);
    const uint32_t b_row = (uint32_t)(warp_n * 32 + (l & 7) + ((l >> 4) & 1) * 8);
    const uint32_t b_co  = (uint32_t)(((l >> 3) & 1) << 4);

    const int arow = tid >> 1;             // A: 128 rows, 2 threads/row
    const int ach  = (tid & 1) * 4;        //   chunks 0-3 or 4-7
    const int brow = tid >> 2;             // B: 64 rows, 4 threads/row
    const int bch  = (tid & 3) * 2;        //   2 chunks each

    auto issue = [&](int s, int kb) {
        const uint32_t st = sbase + (uint32_t)s * SS_STG;
        #pragma unroll
        for (int j = 0; j < 4; ++j) {
            const int ch = ach + j;
            cp16(st + (uint32_t)(arow * RS64 + ch * 16),
                 A + (size_t)arow * lda + kb + ch * 8);
        }
        #pragma unroll
        for (int j = 0; j < 2; ++j) {
            const int ch = bch + j;
            cp16(st + SS_B + (uint32_t)(brow * RS64 + ch * 16),
                 B + (size_t)brow * ldb + kb + ch * 8);
        }
    };

    issue(0, 0);
    CP_COMMIT();

    const int KT = K >> 6;
    for (int kt = 0; kt < KT; ++kt) {
        if (kt + 1 < KT) {
            issue((kt + 1) & 1, (kt + 1) << 6);
            CP_COMMIT();
            CP_WAIT(1);
        } else {
            CP_WAIT(0);
        }
        __syncthreads();

        const uint32_t st = sbase + (uint32_t)((kt & 1) * SS_STG);
        #pragma unroll
        for (int ks = 0; ks < 4; ++ks) {
            uint32_t ah[2][4], bh[2][4];
            #pragma unroll
            for (int bm = 0; bm < 2; ++bm) {
                const uint32_t aaddr = st + (a_row + bm * 16) * RS64 + ks * 32 + a_co;
                ldsm_x4(ah[bm][0], ah[bm][1], ah[bm][2], ah[bm][3], aaddr);
            }
            #pragma unroll
            for (int np = 0; np < 2; ++np) {
                const uint32_t baddr = st + SS_B + (b_row + np * 16) * RS64 + ks * 32 + b_co;
                ldsm_x4(bh[np][0], bh[np][1], bh[np][2], bh[np][3], baddr);
            }
            #pragma unroll
            for (int np = 0; np < 2; ++np)
                #pragma unroll
                for (int bm = 0; bm < 2; ++bm) {
                    mma_f16(acc[bm][np * 2],     ah[bm], bh[np][0], bh[np][1]);
                    mma_f16(acc[bm][np * 2 + 1], ah[bm], bh[np][2], bh[np][3]);
                }
        }
        __syncthreads();
    }
}

// ---------------------------------------------------------------------------
// Kernel 0a: weight preconversion (single fp16)
// ---------------------------------------------------------------------------
__global__ __launch_bounds__(256)
void prep_kernel(const float* __restrict__ w1, const float* __restrict__ wf,
                 const float* __restrict__ ws, const float* __restrict__ wg)
{
    const int idx = blockIdx.x * 256 + threadIdx.x;
    const int NW1 = ICH * KCONV;
    if (idx < NW1) {
        g_w1[idx] = __float2half_rn(w1[idx]);
    } else {
        int j = idx - NW1;
        if (j >= 3 * NFC * ICH) return;
        const int which = j >> 15;
        const int e = j & 32767;
        float v = (which == 0 ? wf : which == 1 ? ws : wg)[e];
        __half h = __float2half_rn(v);
        if (which == 0)      g_wf[e] = h;
        else if (which == 1) g_ws[e] = h;
        else                 g_wg[e] = h;
    }
}

// ---------------------------------------------------------------------------
// Kernel 0b: im2col of x into single fp16
// ---------------------------------------------------------------------------
#define I2C_RS 264
#define I2C_SMEM (64 * I2C_RS * 2)

__global__ __launch_bounds__(256, 1)
void im2col_kernel(const float* __restrict__ x)
{
    extern __shared__ char smraw[];
    __half* sh = (__half*)smraw;

    const int bx = blockIdx.x;
    const int icc = bx & 7;
    const int oh  = (bx >> 3) & 31;
    const int b   = bx >> 8;
    const int t = threadIdx.x;

    #pragma unroll
    for (int it = 0; it < 16; ++it) {
        const int f = t + it * 256;
        const int w4 = f & 63;
        const int kh = (f >> 6) & 7;
        const int i  = f >> 9;
        const float4 v = *(const float4*)&x[((size_t)(b * 64 + icc * 8 + i) * 256 + oh * 8 + kh) * 256 + w4 * 4];
        const int row = i * 8 + kh;
        sh[row * I2C_RS + w4 * 4 + 0] = __float2half_rn(v.x);
        sh[row * I2C_RS + w4 * 4 + 1] = __float2half_rn(v.y);
        sh[row * I2C_RS + w4 * 4 + 2] = __float2half_rn(v.z);
        sh[row * I2C_RS + w4 * 4 + 3] = __float2half_rn(v.w);
    }
    __syncthreads();

    #pragma unroll
    for (int it = 0; it < 8; ++it) {
        const int f = t + it * 256;
        const int kh = f & 7;
        const int i  = (f >> 3) & 7;
        const int ow = f >> 6;
        const int row = i * 8 + kh;
        const size_t r = (size_t)b * 1024 + oh * 32 + ow;
        const size_t kbase = (size_t)(icc * 8 + i) * 64 + kh * 8;
        *(uint4*)&g_x[r * KCONV + kbase] = *(const uint4*)&sh[row * I2C_RS + ow * 8];
    }
}

// ---------------------------------------------------------------------------
// Kernel 1: conv1 GEMM (pure fp16); grid (64 m, 4 n)
// ---------------------------------------------------------------------------
__global__ __launch_bounds__(256, 2)
void conv1_mma_kernel(const float* __restrict__ bnS, const float* __restrict__ bnB)
{
    extern __shared__ char smem[];
    const uint32_t sbase = smem_u32(smem);

    const int m0 = blockIdx.x * 128;
    const int n0 = blockIdx.y * 64;

    float acc[2][4][4] = {};
    gemm_tile_ss(g_x + (size_t)m0 * KCONV, KCONV,
                 g_w1 + (size_t)n0 * KCONV, KCONV,
                 KCONV, sbase, acc);

    const int wid = threadIdx.x >> 5, l = threadIdx.x & 31;
    const int erow0 = m0 + (wid & 3) * 32 + (l >> 2);
    const int ecol0 = n0 + (wid >> 2) * 32 + (l & 3) * 2;
    #pragma unroll
    for (int bm = 0; bm < 2; ++bm) {
        #pragma unroll
        for (int nb = 0; nb < 4; ++nb) {
            const int col = ecol0 + nb * 8;
            const float s0 = bnS[col], s1 = bnS[col + 1];
            const float v0 = bnB[col], v1 = bnB[col + 1];
            const int r0 = erow0 + bm * 16;
            float a0 = fmaxf(acc[bm][nb][0] * s0 + v0, 0.0f);
            float a1 = fmaxf(acc[bm][nb][1] * s1 + v1, 0.0f);
            float a2 = fmaxf(acc[bm][nb][2] * s0 + v0, 0.0f);
            float a3 = fmaxf(acc[bm][nb][3] * s1 + v1, 0.0f);
            *(uint32_t*)&g_y[(size_t)r0 * ICH + col] = packh2(a0, a1);
            *(uint32_t*)&g_y[(size_t)(r0 + 8) * ICH + col] = packh2(a2, a3);
        }
    }
}

// ---------------------------------------------------------------------------
// Kernel 2: projections (pure fp16); grid (64 m, 2 n, 3)
// ---------------------------------------------------------------------------
__global__ __launch_bounds__(256, 2)
void proj_mma_kernel(const float* __restrict__ sf, const float* __restrict__ bf,
                     const float* __restrict__ ss, const float* __restrict__ bs,
                     const float* __restrict__ sg, const float* __restrict__ bg)
{
    extern __shared__ char smem[];
    const uint32_t sbase = smem_u32(smem);

    const int z = blockIdx.z;
    const __half* W = (z == 0) ? g_wf : (z == 1) ? g_ws : g_wg;
    const float* Sv = (z == 0) ? sf : (z == 1) ? ss : sg;
    const float* Bv = (z == 0) ? bf : (z == 1) ? bs : bg;

    const int m0 = blockIdx.x * 128;
    const int n0 = blockIdx.y * 64;

    float acc[2][4][4] = {};
    gemm_tile_ss(g_y + (size_t)m0 * ICH, ICH,
                 W + (size_t)n0 * ICH, ICH,
                 ICH, sbase, acc);

    const int wid = threadIdx.x >> 5, l = threadIdx.x & 31;
    const int erow0 = m0 + (wid & 3) * 32 + (l >> 2);
    const int ecol0 = n0 + (wid >> 2) * 32 + (l & 3) * 2;
    #pragma unroll
    for (int bm = 0; bm < 2; ++bm) {
        #pragma unroll
        for (int nb = 0; nb < 4; ++nb) {
            const int col = ecol0 + nb * 8;
            const float s0 = Sv[col], s1 = Sv[col + 1];
            const float v0 = Bv[col], v1 = Bv[col + 1];
            const int r0 = erow0 + bm * 16;
            float a0 = fmaxf(acc[bm][nb][0] * s0 + v0, 0.0f);
            float a1 = fmaxf(acc[bm][nb][1] * s1 + v1, 0.0f);
            float a2 = fmaxf(acc[bm][nb][2] * s0 + v0, 0.0f);
            float a3 = fmaxf(acc[bm][nb][3] * s1 + v1, 0.0f);
            if (z < 2) {
                __half* Oh = (z == 0) ? g_fai : g_sit;
                *(uint32_t*)&Oh[(size_t)r0 * NFC + col] = packh2(a0, a1);
                *(uint32_t*)&Oh[(size_t)(r0 + 8) * NFC + col] = packh2(a2, a3);
            } else {
                const int bb = r0 >> 10;
                const int n  = r0 & 1023;
                const size_t base = (size_t)bb * NFC * NPIX;
                g_gT[base + (size_t)col * NPIX + n]            = __float2half_rn(a0);
                g_gT[base + (size_t)(col + 1) * NPIX + n]      = __float2half_rn(a1);
                g_gT[base + (size_t)col * NPIX + n + 8]        = __float2half_rn(a2);
                g_gT[base + (size_t)(col + 1) * NPIX + n + 8]  = __float2half_rn(a3);
            }
        }
    }
}

// ---------------------------------------------------------------------------
// Kernel 3: score S = sigmoid(fai . sit); grid (8 m, 16 n, 8 b)
// ---------------------------------------------------------------------------
__global__ __launch_bounds__(256, 2)
void score_mma_kernel()
{
    extern __shared__ char smem[];
    const uint32_t sbase = smem_u32(smem);

    const int b  = blockIdx.z;
    const int m0 = blockIdx.x * 128;
    const int n0 = blockIdx.y * 64;
    const size_t abase = (size_t)b * NPIX * NFC;

    float acc[2][4][4] = {};
    gemm_tile_ss(g_fai + abase + (size_t)m0 * NFC, NFC,
                 g_sit + abase + (size_t)n0 * NFC, NFC,
                 NFC, sbase, acc);

    const size_t sb_out = (size_t)b * NPIX * NPIX;
    const int wid = threadIdx.x >> 5, l = threadIdx.x & 31;
    const int erow0 = m0 + (wid & 3) * 32 + (l >> 2);
    const int ecol0 = n0 + (wid >> 2) * 32 + (l & 3) * 2;
    #pragma unroll
    for (int bm = 0; bm < 2; ++bm) {
        #pragma unroll
        for (int nb = 0; nb < 4; ++nb) {
            const int col = ecol0 + nb * 8;
            const int r0 = erow0 + bm * 16;
            float a0 = 1.0f / (1.0f + expf(-acc[bm][nb][0]));
            float a1 = 1.0f / (1.0f + expf(-acc[bm][nb][1]));
            float a2 = 1.0f / (1.0f + expf(-acc[bm][nb][2]));
            float a3 = 1.0f / (1.0f + expf(-acc[bm][nb][3]));
            *(uint32_t*)&g_S[sb_out + (size_t)r0 * NPIX + col] = packh2(a0, a1);
            *(uint32_t*)&g_S[sb_out + (size_t)(r0 + 8) * NPIX + col] = packh2(a2, a3);
        }
    }
}

// ---------------------------------------------------------------------------
// Kernel 4: att = S @ gamaT, split-K(2); grid (8 m, 2 n, 16)
// ---------------------------------------------------------------------------
__global__ __launch_bounds__(256, 2)
void attn_mma_kernel()
{
    extern __shared__ char smem[];
    const uint32_t sbase = smem_u32(smem);

    const int z  = blockIdx.z;
    const int b  = z >> 1;
    const int ks = z & 1;
    const int m0 = blockIdx.x * 128;
    const int n0 = blockIdx.y * 64;
    const size_t sBase = (size_t)b * NPIX * NPIX;
    const size_t gBase = (size_t)b * NFC * NPIX;
    const int kofs = ks * 512;

    float acc[2][4][4] = {};
    gemm_tile_ss(g_S + sBase + (size_t)m0 * NPIX + kofs, NPIX,
                 g_gT + gBase + (size_t)n0 * NPIX + kofs, NPIX,
                 512, sbase, acc);

    float* outp = ks ? g_att1 : g_att0;
    const int wid = threadIdx.x >> 5, l = threadIdx.x & 31;
    const int erow0 = m0 + (wid & 3) * 32 + (l >> 2);
    const int ecol0 = n0 + (wid >> 2) * 32 + (l & 3) * 2;
    #pragma unroll
    for (int bm = 0; bm < 2; ++bm) {
        #pragma unroll
        for (int nb = 0; nb < 4; ++nb) {
            const int col = ecol0 + nb * 8;
            const int r0 = erow0 + bm * 16;
            float2 o0 = {acc[bm][nb][0], acc[bm][nb][1]};
            float2 o1 = {acc[bm][nb][2], acc[bm][nb][3]};
            *(float2*)&outp[((size_t)b * NPIX + r0) * NFC + col] = o0;
            *(float2*)&outp[((size_t)b * NPIX + r0 + 8) * NFC + col] = o1;
        }
    }
}

// ---------------------------------------------------------------------------
// Kernel 5: bilinear upsample x8 (align_corners), sums split-K partials
// ---------------------------------------------------------------------------
__global__ __launch_bounds__(256)
void upsample_kernel(float* __restrict__ out)
{
    __shared__ float rows[3][32];
    const int gx = blockIdx.x;
    const int yt = gx & 31;
    const int c  = (gx >> 5) & 127;
    const int b  = gx >> 12;
    const int t = threadIdx.x;

    const float sc = 31.0f / 255.0f;
    const int rbase = (int)floorf((float)(yt * 8) * sc);
    if (t < 96) {
        const int rr = t >> 5, xx = t & 31;
        const int r = min(rbase + rr, 31);
        const size_t idx = ((size_t)b * NPIX + r * 32 + xx) * NFC + c;
        rows[rr][xx] = g_att0[idx] + g_att1[idx];
    }
    __syncthreads();

    const int xo = t;
    const float xs = (float)xo * sc;
    const int x0 = (int)floorf(xs);
    const float wx = xs - (float)x0;
    const int x1 = min(x0 + 1, 31);
    const size_t obase = ((size_t)(b * 128 + c)) * 256 * 256;

    #pragma unroll
    for (int i = 0; i < 8; ++i) {
        const int yo = yt * 8 + i;
        const float ysf = (float)yo * sc;
        const int y0 = (int)floorf(ysf);
        const float wy = ysf - (float)y0;
        const int y1 = min(y0 + 1, 31);
        const int r0 = y0 - rbase, r1 = y1 - rbase;
        const float v00 = rows[r0][x0], v01 = rows[r0][x1];
        const float v10 = rows[r1][x0], v11 = rows[r1][x1];
        const float top0 = v00 * (1.0f - wy) + v10 * wy;
        const float top1 = v01 * (1.0f - wy) + v11 * wy;
        out[obase + (size_t)yo * 256 + xo] = top0 * (1.0f - wx) + top1 * wx;
    }
}

// ---------------------------------------------------------------------------
// Launch
// ---------------------------------------------------------------------------
extern "C" void kernel_launch(void* const* d_in, const int* in_sizes, int n_in,
                              void* d_out, int out_size)
{
    const float* x     = (const float*)d_in[0];
    const float* w1    = (const float*)d_in[1];
    const float* bn1_s = (const float*)d_in[2];
    const float* bn1_b = (const float*)d_in[3];
    const float* w_fai = (const float*)d_in[4];
    const float* bnf_s = (const float*)d_in[5];
    const float* bnf_b = (const float*)d_in[6];
    const float* w_sit = (const float*)d_in[7];
    const float* bns_s = (const float*)d_in[8];
    const float* bns_b = (const float*)d_in[9];
    const float* w_gam = (const float*)d_in[10];
    const float* bng_s = (const float*)d_in[11];
    const float* bng_b = (const float*)d_in[12];
    float* out = (float*)d_out;

    static bool attr_done = false;
    if (!attr_done) {
        cudaFuncSetAttribute(conv1_mma_kernel, cudaFuncAttributeMaxDynamicSharedMemorySize, GEMM_SMEM_SS);
        cudaFuncSetAttribute(proj_mma_kernel,  cudaFuncAttributeMaxDynamicSharedMemorySize, GEMM_SMEM_SS);
        cudaFuncSetAttribute(score_mma_kernel, cudaFuncAttributeMaxDynamicSharedMemorySize, GEMM_SMEM_SS);
        cudaFuncSetAttribute(attn_mma_kernel,  cudaFuncAttributeMaxDynamicSharedMemorySize, GEMM_SMEM_SS);
        cudaFuncSetAttribute(im2col_kernel,    cudaFuncAttributeMaxDynamicSharedMemorySize, I2C_SMEM);
        attr_done = true;
    }

    // 0a. weight preconversion (single fp16)
    {
        const int total = ICH * KCONV + 3 * NFC * ICH;
        prep_kernel<<<(total + 255) / 256, 256>>>(w1, w_fai, w_sit, w_gam);
    }
    // 0b. im2col(x) -> single fp16
    im2col_kernel<<<2048, 256, I2C_SMEM>>>(x);
    // 1. conv1 GEMM + BN + ReLU
    {
        dim3 grid(MROWS / 128, ICH / 64);
        conv1_mma_kernel<<<grid, 256, GEMM_SMEM_SS>>>(bn1_s, bn1_b);
    }
    // 2. projections
    {
        dim3 grid(MROWS / 128, NFC / 64, 3);
        proj_mma_kernel<<<grid, 256, GEMM_SMEM_SS>>>(bnf_s, bnf_b, bns_s, bns_b, bng_s, bng_b);
    }
    // 3. S = sigmoid(fai . sit)
    {
        dim3 grid(NPIX / 128, NPIX / 64, BATCH);
        score_mma_kernel<<<grid, 256, GEMM_SMEM_SS>>>();
    }
    // 4. att = S @ gamaT (split-K 2)
    {
        dim3 grid(NPIX / 128, NFC / 64, BATCH * 2);
        attn_mma_kernel<<<grid, 256, GEMM_SMEM_SS>>>();
    }
    // 5. upsample (+ split-K reduce)
    upsample_kernel<<<BATCH * 128 * 32, 256>>>(out);
}

// round 14
// speedup vs baseline: 1.0776x; 1.0776x over previous
#include <cuda_runtime.h>
#include <cuda_fp16.h>
#include <math.h>
#include <stdint.h>

// ---------------------------------------------------------------------------
// Problem constants
// ---------------------------------------------------------------------------
#define BATCH 8
#define ICH   256
#define NFC   128
#define NPIX  1024
#define KCONV 4096
#define MROWS 8192

// ---------------------------------------------------------------------------
// Device scratch (pure fp16 chain)
// ---------------------------------------------------------------------------
__device__ __half g_w1[ICH * KCONV];
__device__ __half g_wf[NFC * ICH];
__device__ __half g_ws[NFC * ICH];
__device__ __half g_wg[NFC * ICH];

__device__ __half g_x[MROWS * KCONV];          // im2col(x)
__device__ __half g_y[MROWS * ICH];            // conv out
__device__ __half g_fai[BATCH * NPIX * NFC];
__device__ __half g_sit[BATCH * NPIX * NFC];
__device__ __half g_gT[BATCH * NFC * NPIX];    // [b][c][m]
__device__ __half g_S[BATCH * NPIX * NPIX];    // [b][n][m]
__device__ float g_att0[BATCH * NPIX * NFC];   // split-K partials
__device__ float g_att1[BATCH * NPIX * NFC];

// ---------------------------------------------------------------------------
// Portable helpers (base sm_103)
// ---------------------------------------------------------------------------
__device__ __forceinline__ uint32_t smem_u32(const void* p) {
    uint32_t a;
    asm("{ .reg .u64 t; cvta.to.shared.u64 t, %1; cvt.u32.u64 %0, t; }" : "=r"(a) : "l"(p));
    return a;
}

__device__ __forceinline__ void cp16(uint32_t saddr, const void* gaddr) {
    asm volatile("cp.async.cg.shared.global [%0], [%1], 16;" :: "r"(saddr), "l"(gaddr));
}
#define CP_COMMIT() asm volatile("cp.async.commit_group;" ::: "memory")
#define CP_WAIT(n)  asm volatile("cp.async.wait_group %0;" :: "n"(n) : "memory")

__device__ __forceinline__ void ldsm_x4(uint32_t& r0, uint32_t& r1, uint32_t& r2, uint32_t& r3,
                                        uint32_t addr) {
    asm volatile("ldmatrix.sync.aligned.m8n8.x4.shared.b16 {%0,%1,%2,%3}, [%4];"
        : "=r"(r0), "=r"(r1), "=r"(r2), "=r"(r3) : "r"(addr));
}

__device__ __forceinline__ void mma_f16(float* c, const uint32_t* a,
                                        uint32_t b0, uint32_t b1) {
    asm volatile(
        "mma.sync.aligned.m16n8k16.row.col.f32.f16.f16.f32 "
        "{%0,%1,%2,%3}, {%4,%5,%6,%7}, {%8,%9}, {%0,%1,%2,%3};"
        : "+f"(c[0]), "+f"(c[1]), "+f"(c[2]), "+f"(c[3])
        : "r"(a[0]), "r"(a[1]), "r"(a[2]), "r"(a[3]), "r"(b0), "r"(b1));
}

__device__ __forceinline__ uint32_t packh2(float a, float b) {
    __half h0 = __float2half_rn(a), h1 = __float2half_rn(b);
    return (uint32_t)__half_as_ushort(h0) | ((uint32_t)__half_as_ushort(h1) << 16);
}

#define RSTRIDE 80

// ---------------------------------------------------------------------------
// 128x64 pure-fp16 GEMM tile (R12 exact: K-tile 32, 2-stage, issue->wait->sync)
//   smem/stage: A[128x32]@0 (10240) + B[64x32]@10240 (5120) = 15360
// ---------------------------------------------------------------------------
#define SS_B  10240
#define SS_STG 15360
#define GEMM_SMEM_SS (2 * SS_STG)   // 30720

__device__ __forceinline__ void gemm_tile_ss(
    const __half* __restrict__ A, int lda,
    const __half* __restrict__ B, int ldb,
    int K, uint32_t sbase, float acc[2][4][4])
{
    const int tid = threadIdx.x;
    const int l = tid & 31;
    const int wid = tid >> 5;
    const int warp_m = wid & 3, warp_n = wid >> 2;
    const int arow = tid >> 2;
    const int q4   = tid & 3;

    const uint32_t a_row = (uint32_t)(warp_m * 32 + (l & 15));
    const uint32_t a_co  = (uint32_t)((l >> 4) << 4);
    const uint32_t b_row = (uint32_t)(warp_n * 32 + (l & 7) + ((l >> 4) & 1) * 8);
    const uint32_t b_co  = (uint32_t)(((l >> 3) & 1) << 4);

    auto issue = [&](int s, int kb) {
        const uint32_t st = sbase + (uint32_t)s * SS_STG;
        #pragma unroll
        for (int j = 0; j < 2; ++j) {
            const int row = arow + j * 64;
            cp16(st + (uint32_t)(row * RSTRIDE + q4 * 16),
                 A + (size_t)row * lda + kb + q4 * 8);
        }
        cp16(st + SS_B + (uint32_t)(arow * RSTRIDE + q4 * 16),
             B + (size_t)arow * ldb + kb + q4 * 8);
    };

    issue(0, 0);
    CP_COMMIT();

    const int KT = K >> 5;
    for (int kt = 0; kt < KT; ++kt) {
        if (kt + 1 < KT) {
            issue((kt + 1) & 1, (kt + 1) << 5);
            CP_COMMIT();
            CP_WAIT(1);
        } else {
            CP_WAIT(0);
        }
        __syncthreads();

        const uint32_t st = sbase + (uint32_t)((kt & 1) * SS_STG);
        #pragma unroll
        for (int ks = 0; ks < 2; ++ks) {
            uint32_t ah[2][4], bh[2][4];
            #pragma unroll
            for (int bm = 0; bm < 2; ++bm) {
                const uint32_t aaddr = st + (a_row + bm * 16) * RSTRIDE + ks * 32 + a_co;
                ldsm_x4(ah[bm][0], ah[bm][1], ah[bm][2], ah[bm][3], aaddr);
            }
            #pragma unroll
            for (int np = 0; np < 2; ++np) {
                const uint32_t baddr = st + SS_B + (b_row + np * 16) * RSTRIDE + ks * 32 + b_co;
                ldsm_x4(bh[np][0], bh[np][1], bh[np][2], bh[np][3], baddr);
            }
            #pragma unroll
            for (int np = 0; np < 2; ++np)
                #pragma unroll
                for (int bm = 0; bm < 2; ++bm) {
                    mma_f16(acc[bm][np * 2],     ah[bm], bh[np][0], bh[np][1]);
                    mma_f16(acc[bm][np * 2 + 1], ah[bm], bh[np][2], bh[np][3]);
                }
        }
        __syncthreads();
    }
}

// ---------------------------------------------------------------------------
// Kernel 0a: weight preconversion (single fp16)
// ---------------------------------------------------------------------------
__global__ __launch_bounds__(256)
void prep_kernel(const float* __restrict__ w1, const float* __restrict__ wf,
                 const float* __restrict__ ws, const float* __restrict__ wg)
{
    const int idx = blockIdx.x * 256 + threadIdx.x;
    const int NW1 = ICH * KCONV;
    if (idx < NW1) {
        g_w1[idx] = __float2half_rn(w1[idx]);
    } else {
        int j = idx - NW1;
        if (j >= 3 * NFC * ICH) return;
        const int which = j >> 15;
        const int e = j & 32767;
        float v = (which == 0 ? wf : which == 1 ? ws : wg)[e];
        __half h = __float2half_rn(v);
        if (which == 0)      g_wf[e] = h;
        else if (which == 1) g_ws[e] = h;
        else                 g_wg[e] = h;
    }
}

// ---------------------------------------------------------------------------
// Kernel 0b: im2col of x into single fp16
// ---------------------------------------------------------------------------
#define I2C_RS 264
#define I2C_SMEM (64 * I2C_RS * 2)

__global__ __launch_bounds__(256, 1)
void im2col_kernel(const float* __restrict__ x)
{
    extern __shared__ char smraw[];
    __half* sh = (__half*)smraw;

    const int bx = blockIdx.x;
    const int icc = bx & 7;
    const int oh  = (bx >> 3) & 31;
    const int b   = bx >> 8;
    const int t = threadIdx.x;

    #pragma unroll
    for (int it = 0; it < 16; ++it) {
        const int f = t + it * 256;
        const int w4 = f & 63;
        const int kh = (f >> 6) & 7;
        const int i  = f >> 9;
        const float4 v = *(const float4*)&x[((size_t)(b * 64 + icc * 8 + i) * 256 + oh * 8 + kh) * 256 + w4 * 4];
        const int row = i * 8 + kh;
        sh[row * I2C_RS + w4 * 4 + 0] = __float2half_rn(v.x);
        sh[row * I2C_RS + w4 * 4 + 1] = __float2half_rn(v.y);
        sh[row * I2C_RS + w4 * 4 + 2] = __float2half_rn(v.z);
        sh[row * I2C_RS + w4 * 4 + 3] = __float2half_rn(v.w);
    }
    __syncthreads();

    #pragma unroll
    for (int it = 0; it < 8; ++it) {
        const int f = t + it * 256;
        const int kh = f & 7;
        const int i  = (f >> 3) & 7;
        const int ow = f >> 6;
        const int row = i * 8 + kh;
        const size_t r = (size_t)b * 1024 + oh * 32 + ow;
        const size_t kbase = (size_t)(icc * 8 + i) * 64 + kh * 8;
        *(uint4*)&g_x[r * KCONV + kbase] = *(const uint4*)&sh[row * I2C_RS + ow * 8];
    }
}

// ---------------------------------------------------------------------------
// Kernel 1: conv1 GEMM (pure fp16); grid (4 n, 64 m) — n fastest for A reuse
// ---------------------------------------------------------------------------
__global__ __launch_bounds__(256, 2)
void conv1_mma_kernel(const float* __restrict__ bnS, const float* __restrict__ bnB)
{
    extern __shared__ char smem[];
    const uint32_t sbase = smem_u32(smem);

    const int n0 = blockIdx.x * 64;
    const int m0 = blockIdx.y * 128;

    float acc[2][4][4] = {};
    gemm_tile_ss(g_x + (size_t)m0 * KCONV, KCONV,
                 g_w1 + (size_t)n0 * KCONV, KCONV,
                 KCONV, sbase, acc);

    const int wid = threadIdx.x >> 5, l = threadIdx.x & 31;
    const int erow0 = m0 + (wid & 3) * 32 + (l >> 2);
    const int ecol0 = n0 + (wid >> 2) * 32 + (l & 3) * 2;
    #pragma unroll
    for (int bm = 0; bm < 2; ++bm) {
        #pragma unroll
        for (int nb = 0; nb < 4; ++nb) {
            const int col = ecol0 + nb * 8;
            const float s0 = bnS[col], s1 = bnS[col + 1];
            const float v0 = bnB[col], v1 = bnB[col + 1];
            const int r0 = erow0 + bm * 16;
            float a0 = fmaxf(acc[bm][nb][0] * s0 + v0, 0.0f);
            float a1 = fmaxf(acc[bm][nb][1] * s1 + v1, 0.0f);
            float a2 = fmaxf(acc[bm][nb][2] * s0 + v0, 0.0f);
            float a3 = fmaxf(acc[bm][nb][3] * s1 + v1, 0.0f);
            *(uint32_t*)&g_y[(size_t)r0 * ICH + col] = packh2(a0, a1);
            *(uint32_t*)&g_y[(size_t)(r0 + 8) * ICH + col] = packh2(a2, a3);
        }
    }
}

// ---------------------------------------------------------------------------
// Kernel 2: projections (pure fp16); grid (64 m, 2 n, 3)
// ---------------------------------------------------------------------------
__global__ __launch_bounds__(256, 2)
void proj_mma_kernel(const float* __restrict__ sf, const float* __restrict__ bf,
                     const float* __restrict__ ss, const float* __restrict__ bs,
                     const float* __restrict__ sg, const float* __restrict__ bg)
{
    extern __shared__ char smem[];
    const uint32_t sbase = smem_u32(smem);

    const int z = blockIdx.z;
    const __half* W = (z == 0) ? g_wf : (z == 1) ? g_ws : g_wg;
    const float* Sv = (z == 0) ? sf : (z == 1) ? ss : sg;
    const float* Bv = (z == 0) ? bf : (z == 1) ? bs : bg;

    const int m0 = blockIdx.x * 128;
    const int n0 = blockIdx.y * 64;

    float acc[2][4][4] = {};
    gemm_tile_ss(g_y + (size_t)m0 * ICH, ICH,
                 W + (size_t)n0 * ICH, ICH,
                 ICH, sbase, acc);

    const int wid = threadIdx.x >> 5, l = threadIdx.x & 31;
    const int erow0 = m0 + (wid & 3) * 32 + (l >> 2);
    const int ecol0 = n0 + (wid >> 2) * 32 + (l & 3) * 2;
    #pragma unroll
    for (int bm = 0; bm < 2; ++bm) {
        #pragma unroll
        for (int nb = 0; nb < 4; ++nb) {
            const int col = ecol0 + nb * 8;
            const float s0 = Sv[col], s1 = Sv[col + 1];
            const float v0 = Bv[col], v1 = Bv[col + 1];
            const int r0 = erow0 + bm * 16;
            float a0 = fmaxf(acc[bm][nb][0] * s0 + v0, 0.0f);
            float a1 = fmaxf(acc[bm][nb][1] * s1 + v1, 0.0f);
            float a2 = fmaxf(acc[bm][nb][2] * s0 + v0, 0.0f);
            float a3 = fmaxf(acc[bm][nb][3] * s1 + v1, 0.0f);
            if (z < 2) {
                __half* Oh = (z == 0) ? g_fai : g_sit;
                *(uint32_t*)&Oh[(size_t)r0 * NFC + col] = packh2(a0, a1);
                *(uint32_t*)&Oh[(size_t)(r0 + 8) * NFC + col] = packh2(a2, a3);
            } else {
                const int bb = r0 >> 10;
                const int n  = r0 & 1023;
                const size_t base = (size_t)bb * NFC * NPIX;
                g_gT[base + (size_t)col * NPIX + n]            = __float2half_rn(a0);
                g_gT[base + (size_t)(col + 1) * NPIX + n]      = __float2half_rn(a1);
                g_gT[base + (size_t)col * NPIX + n + 8]        = __float2half_rn(a2);
                g_gT[base + (size_t)(col + 1) * NPIX + n + 8]  = __float2half_rn(a3);
            }
        }
    }
}

// ---------------------------------------------------------------------------
// Kernel 3: score S = sigmoid(fai . sit); grid (8 m, 16 n, 8 b)
// ---------------------------------------------------------------------------
__global__ __launch_bounds__(256, 2)
void score_mma_kernel()
{
    extern __shared__ char smem[];
    const uint32_t sbase = smem_u32(smem);

    const int b  = blockIdx.z;
    const int m0 = blockIdx.x * 128;
    const int n0 = blockIdx.y * 64;
    const size_t abase = (size_t)b * NPIX * NFC;

    float acc[2][4][4] = {};
    gemm_tile_ss(g_fai + abase + (size_t)m0 * NFC, NFC,
                 g_sit + abase + (size_t)n0 * NFC, NFC,
                 NFC, sbase, acc);

    const size_t sb_out = (size_t)b * NPIX * NPIX;
    const int wid = threadIdx.x >> 5, l = threadIdx.x & 31;
    const int erow0 = m0 + (wid & 3) * 32 + (l >> 2);
    const int ecol0 = n0 + (wid >> 2) * 32 + (l & 3) * 2;
    #pragma unroll
    for (int bm = 0; bm < 2; ++bm) {
        #pragma unroll
        for (int nb = 0; nb < 4; ++nb) {
            const int col = ecol0 + nb * 8;
            const int r0 = erow0 + bm * 16;
            float a0 = 1.0f / (1.0f + __expf(-acc[bm][nb][0]));
            float a1 = 1.0f / (1.0f + __expf(-acc[bm][nb][1]));
            float a2 = 1.0f / (1.0f + __expf(-acc[bm][nb][2]));
            float a3 = 1.0f / (1.0f + __expf(-acc[bm][nb][3]));
            *(uint32_t*)&g_S[sb_out + (size_t)r0 * NPIX + col] = packh2(a0, a1);
            *(uint32_t*)&g_S[sb_out + (size_t)(r0 + 8) * NPIX + col] = packh2(a2, a3);
        }
    }
}

// ---------------------------------------------------------------------------
// Kernel 4: att = S @ gamaT, split-K(2); grid (8 m, 2 n, 16)
// ---------------------------------------------------------------------------
__global__ __launch_bounds__(256, 2)
void attn_mma_kernel()
{
    extern __shared__ char smem[];
    const uint32_t sbase = smem_u32(smem);

    const int z  = blockIdx.z;
    const int b  = z >> 1;
    const int ks = z & 1;
    const int m0 = blockIdx.x * 128;
    const int n0 = blockIdx.y * 64;
    const size_t sBase = (size_t)b * NPIX * NPIX;
    const size_t gBase = (size_t)b * NFC * NPIX;
    const int kofs = ks * 512;

    float acc[2][4][4] = {};
    gemm_tile_ss(g_S + sBase + (size_t)m0 * NPIX + kofs, NPIX,
                 g_gT + gBase + (size_t)n0 * NPIX + kofs, NPIX,
                 512, sbase, acc);

    float* outp = ks ? g_att1 : g_att0;
    const int wid = threadIdx.x >> 5, l = threadIdx.x & 31;
    const int erow0 = m0 + (wid & 3) * 32 + (l >> 2);
    const int ecol0 = n0 + (wid >> 2) * 32 + (l & 3) * 2;
    #pragma unroll
    for (int bm = 0; bm < 2; ++bm) {
        #pragma unroll
        for (int nb = 0; nb < 4; ++nb) {
            const int col = ecol0 + nb * 8;
            const int r0 = erow0 + bm * 16;
            float2 o0 = {acc[bm][nb][0], acc[bm][nb][1]};
            float2 o1 = {acc[bm][nb][2], acc[bm][nb][3]};
            *(float2*)&outp[((size_t)b * NPIX + r0) * NFC + col] = o0;
            *(float2*)&outp[((size_t)b * NPIX + r0 + 8) * NFC + col] = o1;
        }
    }
}

// ---------------------------------------------------------------------------
// Kernel 5: bilinear upsample x8 (align_corners), sums split-K partials
// ---------------------------------------------------------------------------
__global__ __launch_bounds__(256)
void upsample_kernel(float* __restrict__ out)
{
    __shared__ float rows[3][32];
    const int gx = blockIdx.x;
    const int yt = gx & 31;
    const int c  = (gx >> 5) & 127;
    const int b  = gx >> 12;
    const int t = threadIdx.x;

    const float sc = 31.0f / 255.0f;
    const int rbase = (int)floorf((float)(yt * 8) * sc);
    if (t < 96) {
        const int rr = t >> 5, xx = t & 31;
        const int r = min(rbase + rr, 31);
        const size_t idx = ((size_t)b * NPIX + r * 32 + xx) * NFC + c;
        rows[rr][xx] = g_att0[idx] + g_att1[idx];
    }
    __syncthreads();

    const int xo = t;
    const float xs = (float)xo * sc;
    const int x0 = (int)floorf(xs);
    const float wx = xs - (float)x0;
    const int x1 = min(x0 + 1, 31);
    const size_t obase = ((size_t)(b * 128 + c)) * 256 * 256;

    #pragma unroll
    for (int i = 0; i < 8; ++i) {
        const int yo = yt * 8 + i;
        const float ysf = (float)yo * sc;
        const int y0 = (int)floorf(ysf);
        const float wy = ysf - (float)y0;
        const int y1 = min(y0 + 1, 31);
        const int r0 = y0 - rbase, r1 = y1 - rbase;
        const float v00 = rows[r0][x0], v01 = rows[r0][x1];
        const float v10 = rows[r1][x0], v11 = rows[r1][x1];
        const float top0 = v00 * (1.0f - wy) + v10 * wy;
        const float top1 = v01 * (1.0f - wy) + v11 * wy;
        out[obase + (size_t)yo * 256 + xo] = top0 * (1.0f - wx) + top1 * wx;
    }
}

// ---------------------------------------------------------------------------
// Launch
// ---------------------------------------------------------------------------
extern "C" void kernel_launch(void* const* d_in, const int* in_sizes, int n_in,
                              void* d_out, int out_size)
{
    const float* x     = (const float*)d_in[0];
    const float* w1    = (const float*)d_in[1];
    const float* bn1_s = (const float*)d_in[2];
    const float* bn1_b = (const float*)d_in[3];
    const float* w_fai = (const float*)d_in[4];
    const float* bnf_s = (const float*)d_in[5];
    const float* bnf_b = (const float*)d_in[6];
    const float* w_sit = (const float*)d_in[7];
    const float* bns_s = (const float*)d_in[8];
    const float* bns_b = (const float*)d_in[9];
    const float* w_gam = (const float*)d_in[10];
    const float* bng_s = (const float*)d_in[11];
    const float* bng_b = (const float*)d_in[12];
    float* out = (float*)d_out;

    static bool attr_done = false;
    if (!attr_done) {
        cudaFuncSetAttribute(conv1_mma_kernel, cudaFuncAttributeMaxDynamicSharedMemorySize, GEMM_SMEM_SS);
        cudaFuncSetAttribute(proj_mma_kernel,  cudaFuncAttributeMaxDynamicSharedMemorySize, GEMM_SMEM_SS);
        cudaFuncSetAttribute(score_mma_kernel, cudaFuncAttributeMaxDynamicSharedMemorySize, GEMM_SMEM_SS);
        cudaFuncSetAttribute(attn_mma_kernel,  cudaFuncAttributeMaxDynamicSharedMemorySize, GEMM_SMEM_SS);
        cudaFuncSetAttribute(im2col_kernel,    cudaFuncAttributeMaxDynamicSharedMemorySize, I2C_SMEM);
        attr_done = true;
    }

    // 0a. weight preconversion (single fp16)
    {
        const int total = ICH * KCONV + 3 * NFC * ICH;
        prep_kernel<<<(total + 255) / 256, 256>>>(w1, w_fai, w_sit, w_gam);
    }
    // 0b. im2col(x) -> single fp16
    im2col_kernel<<<2048, 256, I2C_SMEM>>>(x);
    // 1. conv1 GEMM + BN + ReLU (n fastest: co-resident CTAs share A tiles in L2)
    {
        dim3 grid(ICH / 64, MROWS / 128);
        conv1_mma_kernel<<<grid, 256, GEMM_SMEM_SS>>>(bn1_s, bn1_b);
    }
    // 2. projections
    {
        dim3 grid(MROWS / 128, NFC / 64, 3);
        proj_mma_kernel<<<grid, 256, GEMM_SMEM_SS>>>(bnf_s, bnf_b, bns_s, bns_b, bng_s, bng_b);
    }
    // 3. S = sigmoid(fai . sit)
    {
        dim3 grid(NPIX / 128, NPIX / 64, BATCH);
        score_mma_kernel<<<grid, 256, GEMM_SMEM_SS>>>();
    }
    // 4. att = S @ gamaT (split-K 2)
    {
        dim3 grid(NPIX / 128, NFC / 64, BATCH * 2);
        attn_mma_kernel<<<grid, 256, GEMM_SMEM_SS>>>();
    }
    // 5. upsample (+ split-K reduce)
    upsample_kernel<<<BATCH * 128 * 32, 256>>>(out);
}

// round 15
// speedup vs baseline: 1.1082x; 1.0284x over previous
#include <cuda_runtime.h>
#include <cuda_fp16.h>
#include <math.h>
#include <stdint.h>

// ---------------------------------------------------------------------------
// Problem constants
// ---------------------------------------------------------------------------
#define BATCH 8
#define ICH   256
#define NFC   128
#define NPIX  1024
#define KCONV 4096
#define MROWS 8192

// ---------------------------------------------------------------------------
// Device scratch (pure fp16 chain)
// ---------------------------------------------------------------------------
__device__ __half g_w1[ICH * KCONV];
__device__ __half g_wf[NFC * ICH];
__device__ __half g_ws[NFC * ICH];
__device__ __half g_wg[NFC * ICH];

__device__ __half g_x[MROWS * KCONV];          // im2col(x)
__device__ __half g_y[MROWS * ICH];            // conv out
__device__ __half g_fai[BATCH * NPIX * NFC];
__device__ __half g_sit[BATCH * NPIX * NFC];
__device__ __half g_gT[BATCH * NFC * NPIX];    // [b][c][m]
__device__ __half g_S[BATCH * NPIX * NPIX];    // [b][n][m]
__device__ float g_att0[BATCH * NPIX * NFC];   // split-K partials
__device__ float g_att1[BATCH * NPIX * NFC];

// ---------------------------------------------------------------------------
// Portable helpers (base sm_103)
// ---------------------------------------------------------------------------
__device__ __forceinline__ uint32_t smem_u32(const void* p) {
    uint32_t a;
    asm("{ .reg .u64 t; cvta.to.shared.u64 t, %1; cvt.u32.u64 %0, t; }" : "=r"(a) : "l"(p));
    return a;
}

__device__ __forceinline__ void cp16(uint32_t saddr, const void* gaddr) {
    asm volatile("cp.async.cg.shared.global [%0], [%1], 16;" :: "r"(saddr), "l"(gaddr));
}
#define CP_COMMIT() asm volatile("cp.async.commit_group;" ::: "memory")
#define CP_WAIT(n)  asm volatile("cp.async.wait_group %0;" :: "n"(n) : "memory")

__device__ __forceinline__ void ldsm_x4(uint32_t& r0, uint32_t& r1, uint32_t& r2, uint32_t& r3,
                                        uint32_t addr) {
    asm volatile("ldmatrix.sync.aligned.m8n8.x4.shared.b16 {%0,%1,%2,%3}, [%4];"
        : "=r"(r0), "=r"(r1), "=r"(r2), "=r"(r3) : "r"(addr));
}

__device__ __forceinline__ void mma_f16(float* c, const uint32_t* a,
                                        uint32_t b0, uint32_t b1) {
    asm volatile(
        "mma.sync.aligned.m16n8k16.row.col.f32.f16.f16.f32 "
        "{%0,%1,%2,%3}, {%4,%5,%6,%7}, {%8,%9}, {%0,%1,%2,%3};"
        : "+f"(c[0]), "+f"(c[1]), "+f"(c[2]), "+f"(c[3])
        : "r"(a[0]), "r"(a[1]), "r"(a[2]), "r"(a[3]), "r"(b0), "r"(b1));
}

__device__ __forceinline__ uint32_t packh2(float a, float b) {
    __half h0 = __float2half_rn(a), h1 = __float2half_rn(b);
    return (uint32_t)__half_as_ushort(h0) | ((uint32_t)__half_as_ushort(h1) << 16);
}

#define RSTRIDE 80

// ---------------------------------------------------------------------------
// 128x64 pure-fp16 GEMM tile (R12 exact: K-tile 32, 2-stage, issue->wait->sync)
//   smem/stage: A[128x32]@0 (10240) + B[64x32]@10240 (5120) = 15360
// ---------------------------------------------------------------------------
#define SS_B  10240
#define SS_STG 15360
#define GEMM_SMEM_SS (2 * SS_STG)   // 30720

__device__ __forceinline__ void gemm_tile_ss(
    const __half* __restrict__ A, int lda,
    const __half* __restrict__ B, int ldb,
    int K, uint32_t sbase, float acc[2][4][4])
{
    const int tid = threadIdx.x;
    const int l = tid & 31;
    const int wid = tid >> 5;
    const int warp_m = wid & 3, warp_n = wid >> 2;
    const int arow = tid >> 2;
    const int q4   = tid & 3;

    const uint32_t a_row = (uint32_t)(warp_m * 32 + (l & 15));
    const uint32_t a_co  = (uint32_t)((l >> 4) << 4);
    const uint32_t b_row = (uint32_t)(warp_n * 32 + (l & 7) + ((l >> 4) & 1) * 8);
    const uint32_t b_co  = (uint32_t)(((l >> 3) & 1) << 4);

    auto issue = [&](int s, int kb) {
        const uint32_t st = sbase + (uint32_t)s * SS_STG;
        #pragma unroll
        for (int j = 0; j < 2; ++j) {
            const int row = arow + j * 64;
            cp16(st + (uint32_t)(row * RSTRIDE + q4 * 16),
                 A + (size_t)row * lda + kb + q4 * 8);
        }
        cp16(st + SS_B + (uint32_t)(arow * RSTRIDE + q4 * 16),
             B + (size_t)arow * ldb + kb + q4 * 8);
    };

    issue(0, 0);
    CP_COMMIT();

    const int KT = K >> 5;
    for (int kt = 0; kt < KT; ++kt) {
        if (kt + 1 < KT) {
            issue((kt + 1) & 1, (kt + 1) << 5);
            CP_COMMIT();
            CP_WAIT(1);
        } else {
            CP_WAIT(0);
        }
        __syncthreads();

        const uint32_t st = sbase + (uint32_t)((kt & 1) * SS_STG);
        #pragma unroll
        for (int ks = 0; ks < 2; ++ks) {
            uint32_t ah[2][4], bh[2][4];
            #pragma unroll
            for (int bm = 0; bm < 2; ++bm) {
                const uint32_t aaddr = st + (a_row + bm * 16) * RSTRIDE + ks * 32 + a_co;
                ldsm_x4(ah[bm][0], ah[bm][1], ah[bm][2], ah[bm][3], aaddr);
            }
            #pragma unroll
            for (int np = 0; np < 2; ++np) {
                const uint32_t baddr = st + SS_B + (b_row + np * 16) * RSTRIDE + ks * 32 + b_co;
                ldsm_x4(bh[np][0], bh[np][1], bh[np][2], bh[np][3], baddr);
            }
            #pragma unroll
            for (int np = 0; np < 2; ++np)
                #pragma unroll
                for (int bm = 0; bm < 2; ++bm) {
                    mma_f16(acc[bm][np * 2],     ah[bm], bh[np][0], bh[np][1]);
                    mma_f16(acc[bm][np * 2 + 1], ah[bm], bh[np][2], bh[np][3]);
                }
        }
        __syncthreads();
    }
}

// ---------------------------------------------------------------------------
// Kernel 0a: weight preconversion (single fp16)
// ---------------------------------------------------------------------------
__global__ __launch_bounds__(256)
void prep_kernel(const float* __restrict__ w1, const float* __restrict__ wf,
                 const float* __restrict__ ws, const float* __restrict__ wg)
{
    const int idx = blockIdx.x * 256 + threadIdx.x;
    const int NW1 = ICH * KCONV;
    if (idx < NW1) {
        g_w1[idx] = __float2half_rn(w1[idx]);
    } else {
        int j = idx - NW1;
        if (j >= 3 * NFC * ICH) return;
        const int which = j >> 15;
        const int e = j & 32767;
        float v = (which == 0 ? wf : which == 1 ? ws : wg)[e];
        __half h = __float2half_rn(v);
        if (which == 0)      g_wf[e] = h;
        else if (which == 1) g_ws[e] = h;
        else                 g_wg[e] = h;
    }
}

// ---------------------------------------------------------------------------
// Kernel 0b: im2col of x into single fp16
// ---------------------------------------------------------------------------
#define I2C_RS 264
#define I2C_SMEM (64 * I2C_RS * 2)

__global__ __launch_bounds__(256, 1)
void im2col_kernel(const float* __restrict__ x)
{
    extern __shared__ char smraw[];
    __half* sh = (__half*)smraw;

    const int bx = blockIdx.x;
    const int icc = bx & 7;
    const int oh  = (bx >> 3) & 31;
    const int b   = bx >> 8;
    const int t = threadIdx.x;

    #pragma unroll
    for (int it = 0; it < 16; ++it) {
        const int f = t + it * 256;
        const int w4 = f & 63;
        const int kh = (f >> 6) & 7;
        const int i  = f >> 9;
        const float4 v = *(const float4*)&x[((size_t)(b * 64 + icc * 8 + i) * 256 + oh * 8 + kh) * 256 + w4 * 4];
        const int row = i * 8 + kh;
        sh[row * I2C_RS + w4 * 4 + 0] = __float2half_rn(v.x);
        sh[row * I2C_RS + w4 * 4 + 1] = __float2half_rn(v.y);
        sh[row * I2C_RS + w4 * 4 + 2] = __float2half_rn(v.z);
        sh[row * I2C_RS + w4 * 4 + 3] = __float2half_rn(v.w);
    }
    __syncthreads();

    #pragma unroll
    for (int it = 0; it < 8; ++it) {
        const int f = t + it * 256;
        const int kh = f & 7;
        const int i  = (f >> 3) & 7;
        const int ow = f >> 6;
        const int row = i * 8 + kh;
        const size_t r = (size_t)b * 1024 + oh * 32 + ow;
        const size_t kbase = (size_t)(icc * 8 + i) * 64 + kh * 8;
        *(uint4*)&g_x[r * KCONV + kbase] = *(const uint4*)&sh[row * I2C_RS + ow * 8];
    }
}

// ---------------------------------------------------------------------------
// Kernel 1: conv1 GEMM (pure fp16); grid (64 m, 4 n)
// ---------------------------------------------------------------------------
__global__ __launch_bounds__(256, 3)
void conv1_mma_kernel(const float* __restrict__ bnS, const float* __restrict__ bnB)
{
    extern __shared__ char smem[];
    const uint32_t sbase = smem_u32(smem);

    const int m0 = blockIdx.x * 128;
    const int n0 = blockIdx.y * 64;

    float acc[2][4][4] = {};
    gemm_tile_ss(g_x + (size_t)m0 * KCONV, KCONV,
                 g_w1 + (size_t)n0 * KCONV, KCONV,
                 KCONV, sbase, acc);

    const int wid = threadIdx.x >> 5, l = threadIdx.x & 31;
    const int erow0 = m0 + (wid & 3) * 32 + (l >> 2);
    const int ecol0 = n0 + (wid >> 2) * 32 + (l & 3) * 2;
    #pragma unroll
    for (int bm = 0; bm < 2; ++bm) {
        #pragma unroll
        for (int nb = 0; nb < 4; ++nb) {
            const int col = ecol0 + nb * 8;
            const float s0 = bnS[col], s1 = bnS[col + 1];
            const float v0 = bnB[col], v1 = bnB[col + 1];
            const int r0 = erow0 + bm * 16;
            float a0 = fmaxf(acc[bm][nb][0] * s0 + v0, 0.0f);
            float a1 = fmaxf(acc[bm][nb][1] * s1 + v1, 0.0f);
            float a2 = fmaxf(acc[bm][nb][2] * s0 + v0, 0.0f);
            float a3 = fmaxf(acc[bm][nb][3] * s1 + v1, 0.0f);
            *(uint32_t*)&g_y[(size_t)r0 * ICH + col] = packh2(a0, a1);
            *(uint32_t*)&g_y[(size_t)(r0 + 8) * ICH + col] = packh2(a2, a3);
        }
    }
}

// ---------------------------------------------------------------------------
// Kernel 2: projections (pure fp16); grid (64 m, 2 n, 3)
// ---------------------------------------------------------------------------
__global__ __launch_bounds__(256, 3)
void proj_mma_kernel(const float* __restrict__ sf, const float* __restrict__ bf,
                     const float* __restrict__ ss, const float* __restrict__ bs,
                     const float* __restrict__ sg, const float* __restrict__ bg)
{
    extern __shared__ char smem[];
    const uint32_t sbase = smem_u32(smem);

    const int z = blockIdx.z;
    const __half* W = (z == 0) ? g_wf : (z == 1) ? g_ws : g_wg;
    const float* Sv = (z == 0) ? sf : (z == 1) ? ss : sg;
    const float* Bv = (z == 0) ? bf : (z == 1) ? bs : bg;

    const int m0 = blockIdx.x * 128;
    const int n0 = blockIdx.y * 64;

    float acc[2][4][4] = {};
    gemm_tile_ss(g_y + (size_t)m0 * ICH, ICH,
                 W + (size_t)n0 * ICH, ICH,
                 ICH, sbase, acc);

    const int wid = threadIdx.x >> 5, l = threadIdx.x & 31;
    const int erow0 = m0 + (wid & 3) * 32 + (l >> 2);
    const int ecol0 = n0 + (wid >> 2) * 32 + (l & 3) * 2;
    #pragma unroll
    for (int bm = 0; bm < 2; ++bm) {
        #pragma unroll
        for (int nb = 0; nb < 4; ++nb) {
            const int col = ecol0 + nb * 8;
            const float s0 = Sv[col], s1 = Sv[col + 1];
            const float v0 = Bv[col], v1 = Bv[col + 1];
            const int r0 = erow0 + bm * 16;
            float a0 = fmaxf(acc[bm][nb][0] * s0 + v0, 0.0f);
            float a1 = fmaxf(acc[bm][nb][1] * s1 + v1, 0.0f);
            float a2 = fmaxf(acc[bm][nb][2] * s0 + v0, 0.0f);
            float a3 = fmaxf(acc[bm][nb][3] * s1 + v1, 0.0f);
            if (z < 2) {
                __half* Oh = (z == 0) ? g_fai : g_sit;
                *(uint32_t*)&Oh[(size_t)r0 * NFC + col] = packh2(a0, a1);
                *(uint32_t*)&Oh[(size_t)(r0 + 8) * NFC + col] = packh2(a2, a3);
            } else {
                const int bb = r0 >> 10;
                const int n  = r0 & 1023;
                const size_t base = (size_t)bb * NFC * NPIX;
                g_gT[base + (size_t)col * NPIX + n]            = __float2half_rn(a0);
                g_gT[base + (size_t)(col + 1) * NPIX + n]      = __float2half_rn(a1);
                g_gT[base + (size_t)col * NPIX + n + 8]        = __float2half_rn(a2);
                g_gT[base + (size_t)(col + 1) * NPIX + n + 8]  = __float2half_rn(a3);
            }
        }
    }
}

// ---------------------------------------------------------------------------
// Kernel 3: score S = sigmoid(fai . sit); grid (8 m, 16 n, 8 b)
// ---------------------------------------------------------------------------
__global__ __launch_bounds__(256, 3)
void score_mma_kernel()
{
    extern __shared__ char smem[];
    const uint32_t sbase = smem_u32(smem);

    const int b  = blockIdx.z;
    const int m0 = blockIdx.x * 128;
    const int n0 = blockIdx.y * 64;
    const size_t abase = (size_t)b * NPIX * NFC;

    float acc[2][4][4] = {};
    gemm_tile_ss(g_fai + abase + (size_t)m0 * NFC, NFC,
                 g_sit + abase + (size_t)n0 * NFC, NFC,
                 NFC, sbase, acc);

    const size_t sb_out = (size_t)b * NPIX * NPIX;
    const int wid = threadIdx.x >> 5, l = threadIdx.x & 31;
    const int erow0 = m0 + (wid & 3) * 32 + (l >> 2);
    const int ecol0 = n0 + (wid >> 2) * 32 + (l & 3) * 2;
    #pragma unroll
    for (int bm = 0; bm < 2; ++bm) {
        #pragma unroll
        for (int nb = 0; nb < 4; ++nb) {
            const int col = ecol0 + nb * 8;
            const int r0 = erow0 + bm * 16;
            float a0 = 1.0f / (1.0f + __expf(-acc[bm][nb][0]));
            float a1 = 1.0f / (1.0f + __expf(-acc[bm][nb][1]));
            float a2 = 1.0f / (1.0f + __expf(-acc[bm][nb][2]));
            float a3 = 1.0f / (1.0f + __expf(-acc[bm][nb][3]));
            *(uint32_t*)&g_S[sb_out + (size_t)r0 * NPIX + col] = packh2(a0, a1);
            *(uint32_t*)&g_S[sb_out + (size_t)(r0 + 8) * NPIX + col] = packh2(a2, a3);
        }
    }
}

// ---------------------------------------------------------------------------
// Kernel 4: att = S @ gamaT, split-K(2); grid (8 m, 2 n, 16)
// ---------------------------------------------------------------------------
__global__ __launch_bounds__(256, 3)
void attn_mma_kernel()
{
    extern __shared__ char smem[];
    const uint32_t sbase = smem_u32(smem);

    const int z  = blockIdx.z;
    const int b  = z >> 1;
    const int ks = z & 1;
    const int m0 = blockIdx.x * 128;
    const int n0 = blockIdx.y * 64;
    const size_t sBase = (size_t)b * NPIX * NPIX;
    const size_t gBase = (size_t)b * NFC * NPIX;
    const int kofs = ks * 512;

    float acc[2][4][4] = {};
    gemm_tile_ss(g_S + sBase + (size_t)m0 * NPIX + kofs, NPIX,
                 g_gT + gBase + (size_t)n0 * NPIX + kofs, NPIX,
                 512, sbase, acc);

    float* outp = ks ? g_att1 : g_att0;
    const int wid = threadIdx.x >> 5, l = threadIdx.x & 31;
    const int erow0 = m0 + (wid & 3) * 32 + (l >> 2);
    const int ecol0 = n0 + (wid >> 2) * 32 + (l & 3) * 2;
    #pragma unroll
    for (int bm = 0; bm < 2; ++bm) {
        #pragma unroll
        for (int nb = 0; nb < 4; ++nb) {
            const int col = ecol0 + nb * 8;
            const int r0 = erow0 + bm * 16;
            float2 o0 = {acc[bm][nb][0], acc[bm][nb][1]};
            float2 o1 = {acc[bm][nb][2], acc[bm][nb][3]};
            *(float2*)&outp[((size_t)b * NPIX + r0) * NFC + col] = o0;
            *(float2*)&outp[((size_t)b * NPIX + r0 + 8) * NFC + col] = o1;
        }
    }
}

// ---------------------------------------------------------------------------
// Kernel 5: bilinear upsample x8 (align_corners), sums split-K partials
// ---------------------------------------------------------------------------
__global__ __launch_bounds__(256)
void upsample_kernel(float* __restrict__ out)
{
    __shared__ float rows[3][32];
    const int gx = blockIdx.x;
    const int yt = gx & 31;
    const int c  = (gx >> 5) & 127;
    const int b  = gx >> 12;
    const int t = threadIdx.x;

    const float sc = 31.0f / 255.0f;
    const int rbase = (int)floorf((float)(yt * 8) * sc);
    if (t < 96) {
        const int rr = t >> 5, xx = t & 31;
        const int r = min(rbase + rr, 31);
        const size_t idx = ((size_t)b * NPIX + r * 32 + xx) * NFC + c;
        rows[rr][xx] = g_att0[idx] + g_att1[idx];
    }
    __syncthreads();

    const int xo = t;
    const float xs = (float)xo * sc;
    const int x0 = (int)floorf(xs);
    const float wx = xs - (float)x0;
    const int x1 = min(x0 + 1, 31);
    const size_t obase = ((size_t)(b * 128 + c)) * 256 * 256;

    #pragma unroll
    for (int i = 0; i < 8; ++i) {
        const int yo = yt * 8 + i;
        const float ysf = (float)yo * sc;
        const int y0 = (int)floorf(ysf);
        const float wy = ysf - (float)y0;
        const int y1 = min(y0 + 1, 31);
        const int r0 = y0 - rbase, r1 = y1 - rbase;
        const float v00 = rows[r0][x0], v01 = rows[r0][x1];
        const float v10 = rows[r1][x0], v11 = rows[r1][x1];
        const float top0 = v00 * (1.0f - wy) + v10 * wy;
        const float top1 = v01 * (1.0f - wy) + v11 * wy;
        out[obase + (size_t)yo * 256 + xo] = top0 * (1.0f - wx) + top1 * wx;
    }
}

// ---------------------------------------------------------------------------
// Launch
// ---------------------------------------------------------------------------
extern "C" void kernel_launch(void* const* d_in, const int* in_sizes, int n_in,
                              void* d_out, int out_size)
{
    const float* x     = (const float*)d_in[0];
    const float* w1    = (const float*)d_in[1];
    const float* bn1_s = (const float*)d_in[2];
    const float* bn1_b = (const float*)d_in[3];
    const float* w_fai = (const float*)d_in[4];
    const float* bnf_s = (const float*)d_in[5];
    const float* bnf_b = (const float*)d_in[6];
    const float* w_sit = (const float*)d_in[7];
    const float* bns_s = (const float*)d_in[8];
    const float* bns_b = (const float*)d_in[9];
    const float* w_gam = (const float*)d_in[10];
    const float* bng_s = (const float*)d_in[11];
    const float* bng_b = (const float*)d_in[12];
    float* out = (float*)d_out;

    static bool attr_done = false;
    if (!attr_done) {
        cudaFuncSetAttribute(conv1_mma_kernel, cudaFuncAttributeMaxDynamicSharedMemorySize, GEMM_SMEM_SS);
        cudaFuncSetAttribute(proj_mma_kernel,  cudaFuncAttributeMaxDynamicSharedMemorySize, GEMM_SMEM_SS);
        cudaFuncSetAttribute(score_mma_kernel, cudaFuncAttributeMaxDynamicSharedMemorySize, GEMM_SMEM_SS);
        cudaFuncSetAttribute(attn_mma_kernel,  cudaFuncAttributeMaxDynamicSharedMemorySize, GEMM_SMEM_SS);
        cudaFuncSetAttribute(im2col_kernel,    cudaFuncAttributeMaxDynamicSharedMemorySize, I2C_SMEM);
        attr_done = true;
    }

    // 0a. weight preconversion (single fp16)
    {
        const int total = ICH * KCONV + 3 * NFC * ICH;
        prep_kernel<<<(total + 255) / 256, 256>>>(w1, w_fai, w_sit, w_gam);
    }
    // 0b. im2col(x) -> single fp16
    im2col_kernel<<<2048, 256, I2C_SMEM>>>(x);
    // 1. conv1 GEMM + BN + ReLU
    {
        dim3 grid(MROWS / 128, ICH / 64);
        conv1_mma_kernel<<<grid, 256, GEMM_SMEM_SS>>>(bn1_s, bn1_b);
    }
    // 2. projections
    {
        dim3 grid(MROWS / 128, NFC / 64, 3);
        proj_mma_kernel<<<grid, 256, GEMM_SMEM_SS>>>(bnf_s, bnf_b, bns_s, bns_b, bng_s, bng_b);
    }
    // 3. S = sigmoid(fai . sit)
    {
        dim3 grid(NPIX / 128, NPIX / 64, BATCH);
        score_mma_kernel<<<grid, 256, GEMM_SMEM_SS>>>();
    }
    // 4. att = S @ gamaT (split-K 2)
    {
        dim3 grid(NPIX / 128, NFC / 64, BATCH * 2);
        attn_mma_kernel<<<grid, 256, GEMM_SMEM_SS>>>();
    }
    // 5. upsample (+ split-K reduce)
    upsample_kernel<<<BATCH * 128 * 32, 256>>>(out);
}